// round 3
// baseline (speedup 1.0000x reference)
#include <cuda_runtime.h>
#include <cstdint>

#define NB 16
#define NP 8192
#define NG 512
#define NK 32
#define TOK 384
#define NM (NB*NG)

typedef unsigned long long ull;

// scratch: centered group points [m][k][3]
__device__ float g_groups[NM * NK * 3];

// ---------- small helpers ----------
__device__ __forceinline__ ull packdup(float a) {
    ull d; asm("mov.b64 %0, {%1, %1};" : "=l"(d) : "f"(a)); return d;
}
__device__ __forceinline__ void fma2(ull& d, ull a, ull b) {
    asm("fma.rn.f32x2 %0, %1, %2, %0;" : "+l"(d) : "l"(a), "l"(b));
}
__device__ __forceinline__ float2 unpack2(ull d) {
    float2 r; asm("mov.b64 {%0, %1}, %2;" : "=f"(r.x), "=f"(r.y) : "l"(d)); return r;
}
__device__ __forceinline__ void atomicMaxF(float* a, float v) {
    if (v >= 0.f) atomicMax((int*)a, __float_as_int(v));
    else          atomicMin((unsigned int*)a, __float_as_uint(v));
}
#define NEG_INF __int_as_float(0xff800000)
#define POS_INF __int_as_float(0x7f800000)

// =====================================================================
// Kernel 1: farthest point sampling. 1 CTA per batch, 1024 threads,
// 8 points per thread held in registers. Writes centers to d_out region.
// =====================================================================
__global__ __launch_bounds__(1024) void fps_kernel(
    const float* __restrict__ pts, float* __restrict__ centers)
{
    int b = blockIdx.x;
    int t = threadIdx.x;
    const float* P = pts + (size_t)b * NP * 3;

    float px[8], py[8], pz[8], md[8];
#pragma unroll
    for (int j = 0; j < 8; j++) {
        int n = j * 1024 + t;
        px[j] = P[n*3+0]; py[j] = P[n*3+1]; pz[j] = P[n*3+2];
        md[j] = 1e10f;
    }

    __shared__ float s_val[32];
    __shared__ int   s_idx[32];
    __shared__ float s_c[3];
    __shared__ int   s_last;

    int last = 0;
    for (int s = 0; s < NG; s++) {
        if (t == 0) {
            float cx = P[last*3+0], cy = P[last*3+1], cz = P[last*3+2];
            s_c[0] = cx; s_c[1] = cy; s_c[2] = cz;
            float* C = centers + ((size_t)b * NG + s) * 3;
            C[0] = cx; C[1] = cy; C[2] = cz;
        }
        __syncthreads();
        float cx = s_c[0], cy = s_c[1], cz = s_c[2];

        float bv = NEG_INF; int bi = 0x7fffffff;
#pragma unroll
        for (int j = 0; j < 8; j++) {
            float dx = px[j] - cx, dy = py[j] - cy, dz = pz[j] - cz;
            float d2 = fmaf(dz, dz, fmaf(dy, dy, __fmul_rn(dx, dx)));
            md[j] = fminf(md[j], d2);
            int n = j * 1024 + t;
            if (md[j] > bv || (md[j] == bv && n < bi)) { bv = md[j]; bi = n; }
        }
        // warp argmax (max val, tie -> min idx)
#pragma unroll
        for (int off = 16; off; off >>= 1) {
            float ov = __shfl_down_sync(0xffffffffu, bv, off);
            int   oi = __shfl_down_sync(0xffffffffu, bi, off);
            if (ov > bv || (ov == bv && oi < bi)) { bv = ov; bi = oi; }
        }
        if ((t & 31) == 0) { s_val[t >> 5] = bv; s_idx[t >> 5] = bi; }
        __syncthreads();
        if (t < 32) {
            bv = s_val[t]; bi = s_idx[t];
#pragma unroll
            for (int off = 16; off; off >>= 1) {
                float ov = __shfl_down_sync(0xffffffffu, bv, off);
                int   oi = __shfl_down_sync(0xffffffffu, bi, off);
                if (ov > bv || (ov == bv && oi < bi)) { bv = ov; bi = oi; }
            }
            if (t == 0) s_last = bi;
        }
        __syncthreads();
        last = s_last;
    }
}

// =====================================================================
// Kernel 2: K=32 nearest neighbors per center + centered group gather.
// 1 CTA (256 thr) per center. d2 row in smem, 32 exact argmin passes
// (tie -> lowest index, matching lax.top_k). Order downstream is
// max-pooled, so only set membership matters.
// =====================================================================
__global__ __launch_bounds__(256) void group_kernel(
    const float* __restrict__ pts, const float* __restrict__ centers)
{
    __shared__ float d2s[NP];
    __shared__ float rv[8];
    __shared__ int   ri[8];
    __shared__ int   sel[NK];

    int m = blockIdx.x;
    int b = m >> 9;           // NG = 512
    int t = threadIdx.x;
    const float* P = pts + (size_t)b * NP * 3;

    float cx = centers[m*3+0], cy = centers[m*3+1], cz = centers[m*3+2];
    float cn = fmaf(cz, cz, fmaf(cy, cy, __fmul_rn(cx, cx)));

#pragma unroll 4
    for (int j = 0; j < 32; j++) {
        int n = j * 256 + t;
        float x = P[n*3+0], y = P[n*3+1], z = P[n*3+2];
        float pn  = fmaf(z, z, fmaf(y, y, __fmul_rn(x, x)));
        float dot = fmaf(cz, z, fmaf(cy, y, __fmul_rn(cx, x)));
        d2s[n] = __fadd_rn(cn, pn) - 2.0f * dot;
    }
    __syncthreads();

    for (int p = 0; p < NK; p++) {
        float bv = POS_INF; int bi = 0x7fffffff;
#pragma unroll
        for (int j = 0; j < 32; j++) {
            int n = j * 256 + t;
            float v = d2s[n];
            if (v < bv || (v == bv && n < bi)) { bv = v; bi = n; }
        }
#pragma unroll
        for (int off = 16; off; off >>= 1) {
            float ov = __shfl_down_sync(0xffffffffu, bv, off);
            int   oi = __shfl_down_sync(0xffffffffu, bi, off);
            if (ov < bv || (ov == bv && oi < bi)) { bv = ov; bi = oi; }
        }
        if ((t & 31) == 0) { rv[t >> 5] = bv; ri[t >> 5] = bi; }
        __syncthreads();
        if (t == 0) {
            float fv = rv[0]; int fi = ri[0];
#pragma unroll
            for (int w = 1; w < 8; w++)
                if (rv[w] < fv || (rv[w] == fv && ri[w] < fi)) { fv = rv[w]; fi = ri[w]; }
            sel[p] = fi;
            d2s[fi] = POS_INF;
        }
        __syncthreads();
    }

    if (t < NK * 3) {
        int k = t / 3, c = t % 3;
        int n = sel[k];
        g_groups[((size_t)m * NK + k) * 3 + c] = P[n*3+c] - centers[m*3+c];
    }
}

// =====================================================================
// Kernel 3: fused MLP per group. 1 CTA (256 thr) per group (32 rows).
// All activations in smem, weights streamed through a smem tile with
// register prefetch. GEMM micro-tile: 4 rows x 4 cols per thread using
// packed fma.rn.f32x2 (2 fp32 FMA / issue).
//   stage1: 3->128 (+bn1,relu)       in smem F1[c][k]
//   stage2: 128->256 (+b2), max->g   in smem F2[c][k], GM[256]
//   stage3: concat(512)->512: g-part k<256 is row-constant (flop saving),
//           f2-part k>=256 full GEMM; +bn2,relu -> F3[c][k]
//   stage4: 512->384 (+b4), max over k -> token[384]
// =====================================================================
__device__ __forceinline__ void ldg_tile(float4* r, const float* __restrict__ W,
                                         int Kdim, int cb, int k0, int t) {
#pragma unroll
    for (int i = 0; i < 4; i++) {
        int f = t + i * 256;
        int c = f >> 3, kq = f & 7;
        r[i] = *(const float4*)(W + (size_t)(cb + c) * Kdim + k0 + kq * 4);
    }
}
__device__ __forceinline__ void sts_tile(float* __restrict__ WT, const float4* r, int t) {
#pragma unroll
    for (int i = 0; i < 4; i++) {
        int f = t + i * 256;
        int c = f >> 3, kq = f & 7;
        WT[(kq*4+0)*128 + c] = r[i].x;
        WT[(kq*4+1)*128 + c] = r[i].y;
        WT[(kq*4+2)*128 + c] = r[i].z;
        WT[(kq*4+3)*128 + c] = r[i].w;
    }
}
__device__ __forceinline__ void mma_tile(ull acc[4][2], const float* __restrict__ A,
                                         const float* __restrict__ WT, int rt, int cc) {
#pragma unroll
    for (int kk = 0; kk < 32; kk++) {
        float4 a = *(const float4*)(A + kk*32 + rt*4);
        ulonglong2 bp = *(const ulonglong2*)(WT + kk*128 + cc);
        ull a0 = packdup(a.x), a1 = packdup(a.y), a2 = packdup(a.z), a3 = packdup(a.w);
        fma2(acc[0][0], a0, bp.x); fma2(acc[0][1], a0, bp.y);
        fma2(acc[1][0], a1, bp.x); fma2(acc[1][1], a1, bp.y);
        fma2(acc[2][0], a2, bp.x); fma2(acc[2][1], a2, bp.y);
        fma2(acc[3][0], a3, bp.x); fma2(acc[3][1], a3, bp.y);
    }
}

#define SMEM_FLOATS 33504
#define SMEM_BYTES  (SMEM_FLOATS * 4)

__global__ __launch_bounds__(256, 1) void mlp_kernel(
    const float* __restrict__ w1,
    const float* __restrict__ bn1g, const float* __restrict__ bn1b,
    const float* __restrict__ bn1m, const float* __restrict__ bn1v,
    const float* __restrict__ w2,  const float* __restrict__ b2,
    const float* __restrict__ w3,
    const float* __restrict__ bn2g, const float* __restrict__ bn2b,
    const float* __restrict__ bn2m, const float* __restrict__ bn2v,
    const float* __restrict__ w4,  const float* __restrict__ b4,
    float* __restrict__ tokens)
{
    extern __shared__ float sm[];
    float* F1  = sm;           // [128][32]
    float* F2  = sm + 4096;    // [256][32]
    float* F3  = sm + 12288;   // [512][32]
    float* WT  = sm + 28672;   // [32][128] weight tile
    float* GM  = sm + 32768;   // [256] group max of f2
    float* TK  = sm + 33024;   // [384] token accum
    float* PTS = sm + 33408;   // [32*3]

    int m = blockIdx.x;
    int t = threadIdx.x;
    int rt = t >> 5;           // row-thread 0..7 -> rows 4rt..4rt+3
    int cc = (t & 31) * 4;     // col offset within 128-col tile

    if (t < NK * 3) PTS[t] = g_groups[(size_t)m * (NK*3) + t];
    GM[t] = NEG_INF;
    if (t < 256) TK[t] = NEG_INF;   // note: t always < 256
    if (t < TOK - 256) TK[256 + t] = NEG_INF;
    __syncthreads();

    // ---- stage 1: 3 -> 128, bn1 + relu ----
    {
        int c  = t >> 1;
        int k0 = (t & 1) * 16;
        float wx = w1[c*3+0], wy = w1[c*3+1], wz = w1[c*3+2];
        float sc = bn1g[c] * rsqrtf(bn1v[c] + 1e-5f);
        float sh = fmaf(-bn1m[c], sc, bn1b[c]);
#pragma unroll
        for (int kk = 0; kk < 16; kk++) {
            int k = k0 + kk;
            float v = fmaf(PTS[k*3+2], wz, fmaf(PTS[k*3+1], wy, PTS[k*3+0] * wx));
            F1[c*32 + k] = fmaxf(fmaf(v, sc, sh), 0.f);
        }
    }

    // ---- stage 2: 128 -> 256, +b2 ; max over rows -> GM ----
    for (int ct = 0; ct < 2; ct++) {
        int cb = ct * 128;
        ull acc[4][2] = {};
        float4 pf[4];
        ldg_tile(pf, w2, 128, cb, 0, t);
        for (int kt = 0; kt < 4; kt++) {
            __syncthreads();
            sts_tile(WT, pf, t);
            __syncthreads();
            if (kt < 3) ldg_tile(pf, w2, 128, cb, (kt+1)*32, t);
            mma_tile(acc, F1 + kt*1024, WT, rt, cc);
        }
#pragma unroll
        for (int j = 0; j < 2; j++) {
            int c0 = cb + cc + 2*j;
            float bb0 = b2[c0], bb1 = b2[c0+1];
            float m0 = NEG_INF, m1 = NEG_INF;
#pragma unroll
            for (int i = 0; i < 4; i++) {
                float2 v = unpack2(acc[i][j]);
                v.x += bb0; v.y += bb1;
                F2[(c0  )*32 + rt*4 + i] = v.x;
                F2[(c0+1)*32 + rt*4 + i] = v.y;
                m0 = fmaxf(m0, v.x); m1 = fmaxf(m1, v.y);
            }
            atomicMaxF(&GM[c0], m0);
            atomicMaxF(&GM[c0+1], m1);
        }
    }

    // ---- stage 3: concat(512) -> 512, bn2 + relu ----
    for (int ct = 0; ct < 4; ct++) {
        int cb = ct * 128;
        ull acc[4][2] = {};
        ull gs[2] = {};
        float4 pf[4];
        ldg_tile(pf, w3, 512, cb, 0, t);
        for (int kt = 0; kt < 16; kt++) {
            __syncthreads();
            sts_tile(WT, pf, t);
            __syncthreads();
            if (kt < 15) ldg_tile(pf, w3, 512, cb, (kt+1)*32, t);
            if (kt < 8) {   // g half of concat: row-constant
#pragma unroll
                for (int kk = 0; kk < 32; kk++) {
                    ull gd = packdup(GM[kt*32 + kk]);
                    ulonglong2 bp = *(const ulonglong2*)(WT + kk*128 + cc);
                    fma2(gs[0], gd, bp.x); fma2(gs[1], gd, bp.y);
                }
            } else {        // f2 half
                mma_tile(acc, F2 + (kt-8)*1024, WT, rt, cc);
            }
        }
#pragma unroll
        for (int j = 0; j < 2; j++) {
            int c0 = cb + cc + 2*j;
            float2 gp = unpack2(gs[j]);
            float sc0 = bn2g[c0  ] * rsqrtf(bn2v[c0  ] + 1e-5f);
            float sh0 = fmaf(-bn2m[c0  ], sc0, bn2b[c0  ]);
            float sc1 = bn2g[c0+1] * rsqrtf(bn2v[c0+1] + 1e-5f);
            float sh1 = fmaf(-bn2m[c0+1], sc1, bn2b[c0+1]);
#pragma unroll
            for (int i = 0; i < 4; i++) {
                float2 v = unpack2(acc[i][j]);
                float x0 = v.x + gp.x, x1 = v.y + gp.y;
                F3[(c0  )*32 + rt*4 + i] = fmaxf(fmaf(x0, sc0, sh0), 0.f);
                F3[(c0+1)*32 + rt*4 + i] = fmaxf(fmaf(x1, sc1, sh1), 0.f);
            }
        }
    }

    // ---- stage 4: 512 -> 384, +b4 ; max over rows -> TK ----
    for (int ct = 0; ct < 3; ct++) {
        int cb = ct * 128;
        ull acc[4][2] = {};
        float4 pf[4];
        ldg_tile(pf, w4, 512, cb, 0, t);
        for (int kt = 0; kt < 16; kt++) {
            __syncthreads();
            sts_tile(WT, pf, t);
            __syncthreads();
            if (kt < 15) ldg_tile(pf, w4, 512, cb, (kt+1)*32, t);
            mma_tile(acc, F3 + kt*1024, WT, rt, cc);
        }
#pragma unroll
        for (int j = 0; j < 2; j++) {
            int c0 = cb + cc + 2*j;
            float bb0 = b4[c0], bb1 = b4[c0+1];
            float m0 = NEG_INF, m1 = NEG_INF;
#pragma unroll
            for (int i = 0; i < 4; i++) {
                float2 v = unpack2(acc[i][j]);
                m0 = fmaxf(m0, v.x + bb0);
                m1 = fmaxf(m1, v.y + bb1);
            }
            atomicMaxF(&TK[c0], m0);
            atomicMaxF(&TK[c0+1], m1);
        }
    }
    __syncthreads();

    tokens[(size_t)m * TOK + t] = TK[t];
    if (t < TOK - 256) tokens[(size_t)m * TOK + 256 + t] = TK[256 + t];
}

// =====================================================================
extern "C" void kernel_launch(void* const* d_in, const int* in_sizes, int n_in,
                              void* d_out, int out_size)
{
    const float* points = (const float*)d_in[0];
    const float* w1     = (const float*)d_in[1];
    const float* bn1g   = (const float*)d_in[2];
    const float* bn1b   = (const float*)d_in[3];
    const float* bn1m   = (const float*)d_in[4];
    const float* bn1v   = (const float*)d_in[5];
    const float* w2     = (const float*)d_in[6];
    const float* b2     = (const float*)d_in[7];
    const float* w3     = (const float*)d_in[8];
    const float* bn2g   = (const float*)d_in[9];
    const float* bn2b   = (const float*)d_in[10];
    const float* bn2m   = (const float*)d_in[11];
    const float* bn2v   = (const float*)d_in[12];
    const float* w4     = (const float*)d_in[13];
    const float* b4     = (const float*)d_in[14];

    float* tokens  = (float*)d_out;                      // [B,G,384]
    float* centers = (float*)d_out + (size_t)NM * TOK;   // [B,G,3]

    fps_kernel<<<NB, 1024>>>(points, centers);
    group_kernel<<<NM, 256>>>(points, centers);

    cudaFuncSetAttribute(mlp_kernel, cudaFuncAttributeMaxDynamicSharedMemorySize, SMEM_BYTES);
    mlp_kernel<<<NM, 256, SMEM_BYTES>>>(w1, bn1g, bn1b, bn1m, bn1v,
                                        w2, b2, w3,
                                        bn2g, bn2b, bn2m, bn2v,
                                        w4, b4, tokens);
}

// round 5
// speedup vs baseline: 2.5600x; 2.5600x over previous
#include <cuda_runtime.h>
#include <cuda_bf16.h>
#include <cstdint>

#define NB 16
#define NP 8192
#define NG 512
#define NK 32
#define TOK 384
#define NM (NB*NG)          // 8192 groups
#define MTOT (NM*NK)        // 262144 rows

#define NEG_INF __int_as_float(0xff800000)
#define POS_INF __int_as_float(0x7f800000)

typedef __nv_bfloat16 bf16;

// ===================== global scratch (bf16 split planes) =====================
__device__ __align__(16) bf16 F1h[(size_t)MTOT*128];
__device__ __align__(16) bf16 F1l[(size_t)MTOT*128];
__device__ __align__(16) bf16 F2h[(size_t)MTOT*256];
__device__ __align__(16) bf16 F2l[(size_t)MTOT*256];
__device__ __align__(16) bf16 F3h[(size_t)MTOT*512];
__device__ __align__(16) bf16 F3l[(size_t)MTOT*512];
__device__ __align__(16) bf16 GMh[(size_t)NM*256];
__device__ __align__(16) bf16 GMl[(size_t)NM*256];
__device__ __align__(16) float G3[(size_t)NM*512];
__device__ __align__(16) bf16 B2h[256*128],  B2l[256*128];
__device__ __align__(16) bf16 W3gh[512*256], W3gl[512*256];
__device__ __align__(16) bf16 W3fh[512*256], W3fl[512*256];
__device__ __align__(16) bf16 W4h[384*512],  W4l[384*512];

// ===================== helpers =====================
__device__ __forceinline__ uint32_t smem_u32(const void* p) {
    uint32_t a;
    asm("{ .reg .u64 t; cvta.to.shared.u64 t, %1; cvt.u32.u64 %0, t; }" : "=r"(a) : "l"(p));
    return a;
}
__device__ __forceinline__ uint32_t swz(uint32_t o) { return o ^ ((o >> 3) & 0x70); }

__device__ __forceinline__ void cp16(uint32_t d, const void* s) {
    asm volatile("cp.async.cg.shared.global [%0], [%1], 16;" :: "r"(d), "l"(s));
}
__device__ __forceinline__ void ldsm4(uint32_t* r, uint32_t addr) {
    asm volatile("ldmatrix.sync.aligned.m8n8.x4.shared.b16 {%0,%1,%2,%3}, [%4];"
        : "=r"(r[0]), "=r"(r[1]), "=r"(r[2]), "=r"(r[3]) : "r"(addr));
}
__device__ __forceinline__ void mma16816(float* d, const uint32_t* a, const uint32_t* b) {
    asm volatile("mma.sync.aligned.m16n8k16.row.col.f32.bf16.bf16.f32 "
        "{%0,%1,%2,%3}, {%4,%5,%6,%7}, {%8,%9}, {%0,%1,%2,%3};"
        : "+f"(d[0]), "+f"(d[1]), "+f"(d[2]), "+f"(d[3])
        : "r"(a[0]), "r"(a[1]), "r"(a[2]), "r"(a[3]), "r"(b[0]), "r"(b[1]));
}
__device__ __forceinline__ void bsplit(float v, uint32_t& hb, uint32_t& lb) {
    bf16 h = __float2bfloat16_rn(v);
    float hf = __bfloat162float(h);
    bf16 l = __float2bfloat16_rn(v - hf);
    hb = (uint32_t)__bfloat16_as_ushort(h);
    lb = (uint32_t)__bfloat16_as_ushort(l);
}
__device__ __forceinline__ void split2(float v0, float v1, uint32_t& hw, uint32_t& lw) {
    uint32_t h0, l0, h1, l1;
    bsplit(v0, h0, l0); bsplit(v1, h1, l1);
    hw = h0 | (h1 << 16); lw = l0 | (l1 << 16);
}
__device__ __forceinline__ void atomicMaxF(float* a, float v) {
    if (v >= 0.f) atomicMax((int*)a, __float_as_int(v));
    else          atomicMin((unsigned int*)a, __float_as_uint(v));
}

// ===================== HMMA GEMM core =====================
// CTA tile M128 x N128, K chunk 64, double buffered.
// smem: buf0 @0, buf1 @65536; each buf: Ah(16K) Al(16K) Bh(16K) Bl(16K).
// Epilogue C (f32, pitch 132) overlays buffers; EXTRA @131072 (4KB).
#define BUFSZ 65536
#define OFF_AL 16384
#define OFF_BH 32768
#define OFF_BL 49152
#define OFF_EXTRA 131072
#define GSMEM (131072 + 4096)
#define CPITCH 132

__device__ __forceinline__ void load_chunk(uint32_t base,
    const bf16* __restrict__ Ah, const bf16* __restrict__ Al,
    const bf16* __restrict__ Bh, const bf16* __restrict__ Bl,
    int arow0, int brow0, int Kdim, int kc)
{
    int t = threadIdx.x;
#pragma unroll
    for (int it = 0; it < 4; it++) {
        int idx = t + it * 256;
        int r = idx >> 3, c = idx & 7;
        uint32_t so = swz((uint32_t)(r * 128 + c * 16));
        size_t ga = (size_t)(arow0 + r) * Kdim + kc * 64 + c * 8;
        size_t gb = (size_t)(brow0 + r) * Kdim + kc * 64 + c * 8;
        cp16(base + so,          Ah + ga);
        cp16(base + OFF_AL + so, Al + ga);
        cp16(base + OFF_BH + so, Bh + gb);
        cp16(base + OFF_BL + so, Bl + gb);
    }
}

__device__ __forceinline__ void gemm_core(float acc[2][8][4],
    const bf16* __restrict__ Ah, const bf16* __restrict__ Al,
    const bf16* __restrict__ Bh, const bf16* __restrict__ Bl,
    int arow0, int brow0, int Kdim, int nchunk)
{
    extern __shared__ char smem[];
    uint32_t sb = smem_u32(smem);
    int t = threadIdx.x, lane = t & 31;
    int wm = (t >> 5) & 3, wn = t >> 7;

    uint32_t a_row = (uint32_t)(lane & 15);
    uint32_t a_kb  = (uint32_t)((lane >> 4) * 16);
    uint32_t b_row = (uint32_t)((lane & 7) + ((lane & 16) ? 8 : 0));
    uint32_t b_kb  = (uint32_t)(((lane >> 3) & 1) * 16);

    load_chunk(sb, Ah, Al, Bh, Bl, arow0, brow0, Kdim, 0);
    asm volatile("cp.async.commit_group;" ::: "memory");

    for (int kc = 0; kc < nchunk; kc++) {
        uint32_t base = sb + (kc & 1) * BUFSZ;
        if (kc + 1 < nchunk) {
            load_chunk(sb + ((kc + 1) & 1) * BUFSZ, Ah, Al, Bh, Bl, arow0, brow0, Kdim, kc + 1);
            asm volatile("cp.async.commit_group;" ::: "memory");
            asm volatile("cp.async.wait_group 1;" ::: "memory");
        } else {
            asm volatile("cp.async.wait_group 0;" ::: "memory");
        }
        __syncthreads();
#pragma unroll
        for (int ks = 0; ks < 4; ks++) {
            uint32_t aH[2][4], aL[2][4], bH[8][2], bL[8][2];
#pragma unroll
            for (int mi = 0; mi < 2; mi++) {
                uint32_t off = swz((uint32_t)((wm * 32 + mi * 16 + a_row) * 128 + ks * 32 + a_kb));
                ldsm4(aH[mi], base + off);
                ldsm4(aL[mi], base + OFF_AL + off);
            }
#pragma unroll
            for (int np = 0; np < 4; np++) {
                uint32_t off = swz((uint32_t)((wn * 64 + np * 16 + b_row) * 128 + ks * 32 + b_kb));
                uint32_t r4[4];
                ldsm4(r4, base + OFF_BH + off);
                bH[np*2][0] = r4[0]; bH[np*2][1] = r4[1];
                bH[np*2+1][0] = r4[2]; bH[np*2+1][1] = r4[3];
                ldsm4(r4, base + OFF_BL + off);
                bL[np*2][0] = r4[0]; bL[np*2][1] = r4[1];
                bL[np*2+1][0] = r4[2]; bL[np*2+1][1] = r4[3];
            }
#pragma unroll
            for (int mi = 0; mi < 2; mi++)
#pragma unroll
                for (int ni = 0; ni < 8; ni++) {
                    mma16816(acc[mi][ni], aH[mi], bH[ni]);
                    mma16816(acc[mi][ni], aH[mi], bL[ni]);
                    mma16816(acc[mi][ni], aL[mi], bH[ni]);
                }
        }
        __syncthreads();
    }
}

// dump accumulators to smem C[128][CPITCH] f32
__device__ __forceinline__ void store_C(float acc[2][8][4]) {
    extern __shared__ char smem[];
    float* C = (float*)smem;
    int t = threadIdx.x, lane = t & 31;
    int wm = (t >> 5) & 3, wn = t >> 7;
    int r0 = wm * 32 + (lane >> 2), c0 = wn * 64 + (lane & 3) * 2;
#pragma unroll
    for (int mi = 0; mi < 2; mi++)
#pragma unroll
        for (int ni = 0; ni < 8; ni++) {
            int r = r0 + mi * 16, c = c0 + ni * 8;
            C[r * CPITCH + c]           = acc[mi][ni][0];
            C[r * CPITCH + c + 1]       = acc[mi][ni][1];
            C[(r + 8) * CPITCH + c]     = acc[mi][ni][2];
            C[(r + 8) * CPITCH + c + 1] = acc[mi][ni][3];
        }
    __syncthreads();
}

// ===================== prep: split weights to bf16 planes =====================
__global__ void prep_kernel(const float* __restrict__ w2, const float* __restrict__ w3,
                            const float* __restrict__ w4)
{
    int i = blockIdx.x * 256 + threadIdx.x;
    int stride = gridDim.x * 256;
    for (int j = i; j < 256*128; j += stride) {
        uint32_t h, l; bsplit(w2[j], h, l);
        B2h[j] = __ushort_as_bfloat16((unsigned short)h);
        B2l[j] = __ushort_as_bfloat16((unsigned short)l);
    }
    for (int j = i; j < 512*512; j += stride) {
        int n = j >> 9, k = j & 511;
        uint32_t h, l; bsplit(w3[j], h, l);
        if (k < 256) {
            W3gh[n*256 + k] = __ushort_as_bfloat16((unsigned short)h);
            W3gl[n*256 + k] = __ushort_as_bfloat16((unsigned short)l);
        } else {
            W3fh[n*256 + k - 256] = __ushort_as_bfloat16((unsigned short)h);
            W3fl[n*256 + k - 256] = __ushort_as_bfloat16((unsigned short)l);
        }
    }
    for (int j = i; j < 384*512; j += stride) {
        uint32_t h, l; bsplit(w4[j], h, l);
        W4h[j] = __ushort_as_bfloat16((unsigned short)h);
        W4l[j] = __ushort_as_bfloat16((unsigned short)l);
    }
}

// ===================== FPS (points in smem) =====================
__global__ __launch_bounds__(1024) void fps_kernel(
    const float* __restrict__ pts, float* __restrict__ centers)
{
    extern __shared__ float sp[];   // [NP*3]
    int b = blockIdx.x;
    int t = threadIdx.x;
    const float* P = pts + (size_t)b * NP * 3;

    for (int idx = t; idx < NP * 3; idx += 1024) sp[idx] = P[idx];
    __syncthreads();

    float px[8], py[8], pz[8], md[8];
#pragma unroll
    for (int j = 0; j < 8; j++) {
        int n = j * 1024 + t;
        px[j] = sp[n*3+0]; py[j] = sp[n*3+1]; pz[j] = sp[n*3+2];
        md[j] = 1e10f;
    }

    __shared__ float s_val[32];
    __shared__ int   s_idx[32];
    __shared__ float s_c[3];
    __shared__ int   s_last;

    int last = 0;
    for (int s = 0; s < NG; s++) {
        if (t == 0) {
            float cx = sp[last*3+0], cy = sp[last*3+1], cz = sp[last*3+2];
            s_c[0] = cx; s_c[1] = cy; s_c[2] = cz;
            float* C = centers + ((size_t)b * NG + s) * 3;
            C[0] = cx; C[1] = cy; C[2] = cz;
        }
        __syncthreads();
        float cx = s_c[0], cy = s_c[1], cz = s_c[2];

        float bv = NEG_INF; int bi = 0x7fffffff;
#pragma unroll
        for (int j = 0; j < 8; j++) {
            float dx = px[j] - cx, dy = py[j] - cy, dz = pz[j] - cz;
            float d2 = fmaf(dz, dz, fmaf(dy, dy, __fmul_rn(dx, dx)));
            md[j] = fminf(md[j], d2);
            int n = j * 1024 + t;
            if (md[j] > bv || (md[j] == bv && n < bi)) { bv = md[j]; bi = n; }
        }
#pragma unroll
        for (int off = 16; off; off >>= 1) {
            float ov = __shfl_down_sync(0xffffffffu, bv, off);
            int   oi = __shfl_down_sync(0xffffffffu, bi, off);
            if (ov > bv || (ov == bv && oi < bi)) { bv = ov; bi = oi; }
        }
        if ((t & 31) == 0) { s_val[t >> 5] = bv; s_idx[t >> 5] = bi; }
        __syncthreads();
        if (t < 32) {
            bv = s_val[t]; bi = s_idx[t];
#pragma unroll
            for (int off = 16; off; off >>= 1) {
                float ov = __shfl_down_sync(0xffffffffu, bv, off);
                int   oi = __shfl_down_sync(0xffffffffu, bi, off);
                if (ov > bv || (ov == bv && oi < bi)) { bv = ov; bi = oi; }
            }
            if (t == 0) s_last = bi;
        }
        __syncthreads();
        last = s_last;
    }
}

// ===================== grouping + stage1 (3->128, bn1+relu, split) =====================
__global__ __launch_bounds__(256) void group_kernel(
    const float* __restrict__ pts, const float* __restrict__ centers,
    const float* __restrict__ w1,
    const float* __restrict__ bn1g, const float* __restrict__ bn1b,
    const float* __restrict__ bn1m, const float* __restrict__ bn1v)
{
    __shared__ float d2s[NP];
    __shared__ float rv[8];
    __shared__ int   ri[8];
    __shared__ int   sel[NK];
    __shared__ float PTS[NK*3];

    int m = blockIdx.x;
    int b = m >> 9;
    int t = threadIdx.x;
    const float* P = pts + (size_t)b * NP * 3;

    float cx = centers[m*3+0], cy = centers[m*3+1], cz = centers[m*3+2];
    float cn = fmaf(cz, cz, fmaf(cy, cy, __fmul_rn(cx, cx)));

#pragma unroll 4
    for (int j = 0; j < 32; j++) {
        int n = j * 256 + t;
        float x = P[n*3+0], y = P[n*3+1], z = P[n*3+2];
        float pn  = fmaf(z, z, fmaf(y, y, __fmul_rn(x, x)));
        float dot = fmaf(cz, z, fmaf(cy, y, __fmul_rn(cx, x)));
        d2s[n] = __fadd_rn(cn, pn) - 2.0f * dot;
    }
    __syncthreads();

    for (int p = 0; p < NK; p++) {
        float bv = POS_INF; int bi = 0x7fffffff;
#pragma unroll
        for (int j = 0; j < 32; j++) {
            int n = j * 256 + t;
            float v = d2s[n];
            if (v < bv || (v == bv && n < bi)) { bv = v; bi = n; }
        }
#pragma unroll
        for (int off = 16; off; off >>= 1) {
            float ov = __shfl_down_sync(0xffffffffu, bv, off);
            int   oi = __shfl_down_sync(0xffffffffu, bi, off);
            if (ov < bv || (ov == bv && oi < bi)) { bv = ov; bi = oi; }
        }
        if ((t & 31) == 0) { rv[t >> 5] = bv; ri[t >> 5] = bi; }
        __syncthreads();
        if (t == 0) {
            float fv = rv[0]; int fi = ri[0];
#pragma unroll
            for (int w = 1; w < 8; w++)
                if (rv[w] < fv || (rv[w] == fv && ri[w] < fi)) { fv = rv[w]; fi = ri[w]; }
            sel[p] = fi;
            d2s[fi] = POS_INF;
        }
        __syncthreads();
    }

    if (t < NK * 3) {
        int k = t / 3, c = t % 3;
        int n = sel[k];
        float cv = (c == 0) ? cx : (c == 1) ? cy : cz;
        PTS[t] = P[n*3+c] - cv;
    }
    __syncthreads();

    {
        int c  = t >> 1;
        int k0 = (t & 1) * 16;
        float wx = w1[c*3+0], wy = w1[c*3+1], wz = w1[c*3+2];
        float sc = bn1g[c] * rsqrtf(bn1v[c] + 1e-5f);
        float sh = fmaf(-bn1m[c], sc, bn1b[c]);
#pragma unroll
        for (int kk = 0; kk < 16; kk++) {
            int k = k0 + kk;
            float v = fmaf(PTS[k*3+2], wz, fmaf(PTS[k*3+1], wy, PTS[k*3+0] * wx));
            v = fmaxf(fmaf(v, sc, sh), 0.f);
            uint32_t h, l; bsplit(v, h, l);
            size_t o = ((size_t)m * NK + k) * 128 + c;
            F1h[o] = __ushort_as_bfloat16((unsigned short)h);
            F1l[o] = __ushort_as_bfloat16((unsigned short)l);
        }
    }
}

// ===================== GEMM kernels =====================
// gemm2: F2 = F1 @ W2^T + b2 ; GM = per-group max of F2
__global__ __launch_bounds__(256) void gemm2_kernel(const float* __restrict__ b2)
{
    int mtile = blockIdx.x >> 1, nt = blockIdx.x & 1;
    float acc[2][8][4] = {};
    gemm_core(acc, F1h, F1l, B2h, B2l, mtile*128, nt*128, 128, 2);
    store_C(acc);

    extern __shared__ char smem[];
    float* C   = (float*)smem;
    float* sGM = (float*)(smem + OFF_EXTRA);
    int t = threadIdx.x;
    sGM[t] = NEG_INF; sGM[t + 256] = NEG_INF;
    __syncthreads();

    int r = t >> 1, h = t & 1, gi = r >> 5;
    size_t mrow = (size_t)mtile*128 + r;
#pragma unroll 8
    for (int i = 0; i < 32; i++) {
        int c = h*64 + i*2;
        float v0 = C[r*CPITCH + c]     + b2[nt*128 + c];
        float v1 = C[r*CPITCH + c + 1] + b2[nt*128 + c + 1];
        uint32_t hw, lw; split2(v0, v1, hw, lw);
        *(uint32_t*)(F2h + mrow*256 + nt*128 + c) = hw;
        *(uint32_t*)(F2l + mrow*256 + nt*128 + c) = lw;
        atomicMaxF(&sGM[gi*128 + c], v0);
        atomicMaxF(&sGM[gi*128 + c + 1], v1);
    }
    __syncthreads();
#pragma unroll
    for (int e = t; e < 512; e += 256) {
        int gi2 = e >> 7, c = e & 127;
        int g = mtile*4 + gi2;
        uint32_t hb, lb; bsplit(sGM[e], hb, lb);
        GMh[(size_t)g*256 + nt*128 + c] = __ushort_as_bfloat16((unsigned short)hb);
        GMl[(size_t)g*256 + nt*128 + c] = __ushort_as_bfloat16((unsigned short)lb);
    }
}

// gemm3g: G3 = GM @ W3g^T  (M = 8192 group rows)
__global__ __launch_bounds__(256) void gemm3g_kernel()
{
    int mtile = blockIdx.x >> 2, nt = blockIdx.x & 3;
    float acc[2][8][4] = {};
    gemm_core(acc, GMh, GMl, W3gh, W3gl, mtile*128, nt*128, 256, 4);
    store_C(acc);

    extern __shared__ char smem[];
    float* C = (float*)smem;
    int t = threadIdx.x;
    int r = t >> 1, h = t & 1;
    size_t grow = (size_t)mtile*128 + r;
#pragma unroll 8
    for (int i = 0; i < 32; i++) {
        int c = h*64 + i*2;
        *(float2*)(G3 + grow*512 + nt*128 + c) =
            make_float2(C[r*CPITCH + c], C[r*CPITCH + c + 1]);
    }
}

// gemm3f: F3 = relu(bn2(F2 @ W3f^T + G3))
__global__ __launch_bounds__(256) void gemm3f_kernel(
    const float* __restrict__ bn2g, const float* __restrict__ bn2b,
    const float* __restrict__ bn2m, const float* __restrict__ bn2v)
{
    int mtile = blockIdx.x >> 2, nt = blockIdx.x & 3;
    float acc[2][8][4] = {};
    gemm_core(acc, F2h, F2l, W3fh, W3fl, mtile*128, nt*128, 256, 4);
    store_C(acc);

    extern __shared__ char smem[];
    float* C   = (float*)smem;
    float* sSC = (float*)(smem + OFF_EXTRA);          // [128]
    float* sSH = sSC + 128;                           // [128]
    float* sG  = sSH + 128;                           // [4][128]
    int t = threadIdx.x;
    if (t < 128) {
        int nl = nt*128 + t;
        float sc = bn2g[nl] * rsqrtf(bn2v[nl] + 1e-5f);
        sSC[t] = sc;
        sSH[t] = fmaf(-bn2m[nl], sc, bn2b[nl]);
    }
#pragma unroll
    for (int e = t; e < 512; e += 256) {
        int gi = e >> 7, c = e & 127;
        sG[e] = G3[(size_t)(mtile*4 + gi)*512 + nt*128 + c];
    }
    __syncthreads();

    int r = t >> 1, h = t & 1, gi = r >> 5;
    size_t mrow = (size_t)mtile*128 + r;
#pragma unroll 8
    for (int i = 0; i < 32; i++) {
        int c = h*64 + i*2;
        float v0 = fmaxf(fmaf(C[r*CPITCH + c]     + sG[gi*128 + c],     sSC[c],     sSH[c]),     0.f);
        float v1 = fmaxf(fmaf(C[r*CPITCH + c + 1] + sG[gi*128 + c + 1], sSC[c + 1], sSH[c + 1]), 0.f);
        uint32_t hw, lw; split2(v0, v1, hw, lw);
        *(uint32_t*)(F3h + mrow*512 + nt*128 + c) = hw;
        *(uint32_t*)(F3l + mrow*512 + nt*128 + c) = lw;
    }
}

// gemm4: tokens = per-group max of (F3 @ W4^T + b4)
__global__ __launch_bounds__(256) void gemm4_kernel(const float* __restrict__ b4,
                                                    float* __restrict__ tokens)
{
    int mtile = blockIdx.x / 3, nt = blockIdx.x % 3;
    float acc[2][8][4] = {};
    gemm_core(acc, F3h, F3l, W4h, W4l, mtile*128, nt*128, 512, 8);
    store_C(acc);

    extern __shared__ char smem[];
    float* C   = (float*)smem;
    float* sTK = (float*)(smem + OFF_EXTRA);
    int t = threadIdx.x;
    sTK[t] = NEG_INF; sTK[t + 256] = NEG_INF;
    __syncthreads();

    int r = t >> 1, h = t & 1, gi = r >> 5;
#pragma unroll 8
    for (int i = 0; i < 32; i++) {
        int c = h*64 + i*2;
        float v0 = C[r*CPITCH + c]     + b4[nt*128 + c];
        float v1 = C[r*CPITCH + c + 1] + b4[nt*128 + c + 1];
        atomicMaxF(&sTK[gi*128 + c], v0);
        atomicMaxF(&sTK[gi*128 + c + 1], v1);
    }
    __syncthreads();
#pragma unroll
    for (int e = t; e < 512; e += 256) {
        int gi2 = e >> 7, c = e & 127;
        int g = mtile*4 + gi2;
        tokens[(size_t)g*TOK + nt*128 + c] = sTK[e];
    }
}

// =====================================================================
extern "C" void kernel_launch(void* const* d_in, const int* in_sizes, int n_in,
                              void* d_out, int out_size)
{
    const float* points = (const float*)d_in[0];
    const float* w1     = (const float*)d_in[1];
    const float* bn1g   = (const float*)d_in[2];
    const float* bn1b   = (const float*)d_in[3];
    const float* bn1m   = (const float*)d_in[4];
    const float* bn1v   = (const float*)d_in[5];
    const float* w2     = (const float*)d_in[6];
    const float* b2     = (const float*)d_in[7];
    const float* w3     = (const float*)d_in[8];
    const float* bn2g   = (const float*)d_in[9];
    const float* bn2b   = (const float*)d_in[10];
    const float* bn2m   = (const float*)d_in[11];
    const float* bn2v   = (const float*)d_in[12];
    const float* w4     = (const float*)d_in[13];
    const float* b4     = (const float*)d_in[14];

    float* tokens  = (float*)d_out;                      // [B,G,384]
    float* centers = (float*)d_out + (size_t)NM * TOK;   // [B,G,3]

    static bool attr_done = false;
    if (!attr_done) {
        cudaFuncSetAttribute(fps_kernel,    cudaFuncAttributeMaxDynamicSharedMemorySize, NP*3*4);
        cudaFuncSetAttribute(gemm2_kernel,  cudaFuncAttributeMaxDynamicSharedMemorySize, GSMEM);
        cudaFuncSetAttribute(gemm3g_kernel, cudaFuncAttributeMaxDynamicSharedMemorySize, GSMEM);
        cudaFuncSetAttribute(gemm3f_kernel, cudaFuncAttributeMaxDynamicSharedMemorySize, GSMEM);
        cudaFuncSetAttribute(gemm4_kernel,  cudaFuncAttributeMaxDynamicSharedMemorySize, GSMEM);
        attr_done = true;
    }

    prep_kernel<<<256, 256>>>(w2, w3, w4);
    fps_kernel<<<NB, 1024, NP*3*4>>>(points, centers);
    group_kernel<<<NM, 256>>>(points, centers, w1, bn1g, bn1b, bn1m, bn1v);
    gemm2_kernel <<<4096, 256, GSMEM>>>(b2);
    gemm3g_kernel<<<256,  256, GSMEM>>>();
    gemm3f_kernel<<<8192, 256, GSMEM>>>(bn2g, bn2b, bn2m, bn2v);
    gemm4_kernel <<<6144, 256, GSMEM>>>(b4, tokens);
}

// round 6
// speedup vs baseline: 3.6147x; 1.4120x over previous
#include <cuda_runtime.h>
#include <cuda_bf16.h>
#include <cstdint>

#define NB 16
#define NP 8192
#define NG 512
#define NK 32
#define TOK 384
#define NM (NB*NG)          // 8192 groups
#define MTOT (NM*NK)        // 262144 rows

#define NEG_INF __int_as_float(0xff800000)
#define POS_INF __int_as_float(0x7f800000)

typedef __nv_bfloat16 bf16;

// ===================== global scratch (bf16 split planes) =====================
__device__ __align__(16) bf16 F1h[(size_t)MTOT*128];
__device__ __align__(16) bf16 F1l[(size_t)MTOT*128];
__device__ __align__(16) bf16 F2h[(size_t)MTOT*256];
__device__ __align__(16) bf16 F2l[(size_t)MTOT*256];
__device__ __align__(16) bf16 F3h[(size_t)MTOT*512];
__device__ __align__(16) bf16 F3l[(size_t)MTOT*512];
__device__ __align__(16) bf16 GMh[(size_t)NM*256];
__device__ __align__(16) bf16 GMl[(size_t)NM*256];
__device__ __align__(16) float G3[(size_t)NM*512];
__device__ __align__(16) bf16 B2h[256*128],  B2l[256*128];
__device__ __align__(16) bf16 W3gh[512*256], W3gl[512*256];
__device__ __align__(16) bf16 W3fh[512*256], W3fl[512*256];
__device__ __align__(16) bf16 W4h[384*512],  W4l[384*512];

// ===================== helpers =====================
__device__ __forceinline__ uint32_t smem_u32(const void* p) {
    uint32_t a;
    asm("{ .reg .u64 t; cvta.to.shared.u64 t, %1; cvt.u32.u64 %0, t; }" : "=r"(a) : "l"(p));
    return a;
}
__device__ __forceinline__ uint32_t swz(uint32_t o) { return o ^ ((o >> 3) & 0x70); }

__device__ __forceinline__ void cp16(uint32_t d, const void* s) {
    asm volatile("cp.async.cg.shared.global [%0], [%1], 16;" :: "r"(d), "l"(s));
}
__device__ __forceinline__ void ldsm4(uint32_t* r, uint32_t addr) {
    asm volatile("ldmatrix.sync.aligned.m8n8.x4.shared.b16 {%0,%1,%2,%3}, [%4];"
        : "=r"(r[0]), "=r"(r[1]), "=r"(r[2]), "=r"(r[3]) : "r"(addr));
}
__device__ __forceinline__ void mma16816(float* d, const uint32_t* a, const uint32_t* b) {
    asm volatile("mma.sync.aligned.m16n8k16.row.col.f32.bf16.bf16.f32 "
        "{%0,%1,%2,%3}, {%4,%5,%6,%7}, {%8,%9}, {%0,%1,%2,%3};"
        : "+f"(d[0]), "+f"(d[1]), "+f"(d[2]), "+f"(d[3])
        : "r"(a[0]), "r"(a[1]), "r"(a[2]), "r"(a[3]), "r"(b[0]), "r"(b[1]));
}
__device__ __forceinline__ void bsplit(float v, uint32_t& hb, uint32_t& lb) {
    bf16 h = __float2bfloat16_rn(v);
    float hf = __bfloat162float(h);
    bf16 l = __float2bfloat16_rn(v - hf);
    hb = (uint32_t)__bfloat16_as_ushort(h);
    lb = (uint32_t)__bfloat16_as_ushort(l);
}
__device__ __forceinline__ void split2(float v0, float v1, uint32_t& hw, uint32_t& lw) {
    uint32_t h0, l0, h1, l1;
    bsplit(v0, h0, l0); bsplit(v1, h1, l1);
    hw = h0 | (h1 << 16); lw = l0 | (l1 << 16);
}

// ===================== HMMA GEMM core =====================
// CTA tile M128 x N128, K chunk 64, SINGLE 64KB buffer:
// Ah @0, Al @16K, Bh @32K, Bl @48K. 2 CTAs/SM (reg-capped at 128).
#define OFF_AL 16384
#define OFF_BH 32768
#define OFF_BL 49152
#define GSMEM 65536

__device__ __forceinline__ void load_chunk(uint32_t base,
    const bf16* __restrict__ Ah, const bf16* __restrict__ Al,
    const bf16* __restrict__ Bh, const bf16* __restrict__ Bl,
    int arow0, int brow0, int Kdim, int kc)
{
    int t = threadIdx.x;
#pragma unroll
    for (int it = 0; it < 4; it++) {
        int idx = t + it * 256;
        int r = idx >> 3, c = idx & 7;
        uint32_t so = swz((uint32_t)(r * 128 + c * 16));
        size_t ga = (size_t)(arow0 + r) * Kdim + kc * 64 + c * 8;
        size_t gb = (size_t)(brow0 + r) * Kdim + kc * 64 + c * 8;
        cp16(base + so,          Ah + ga);
        cp16(base + OFF_AL + so, Al + ga);
        cp16(base + OFF_BH + so, Bh + gb);
        cp16(base + OFF_BL + so, Bl + gb);
    }
    asm volatile("cp.async.commit_group;" ::: "memory");
}

__device__ __forceinline__ void gemm_core(float acc[2][8][4],
    const bf16* __restrict__ Ah, const bf16* __restrict__ Al,
    const bf16* __restrict__ Bh, const bf16* __restrict__ Bl,
    int arow0, int brow0, int Kdim, int nchunk)
{
    extern __shared__ char smem[];
    uint32_t sb = smem_u32(smem);
    int t = threadIdx.x, lane = t & 31;
    int wm = (t >> 5) & 3, wn = t >> 7;

    uint32_t a_row = (uint32_t)(lane & 15);
    uint32_t a_kb  = (uint32_t)((lane >> 4) * 16);
    uint32_t b_row = (uint32_t)((lane & 7) + ((lane & 16) ? 8 : 0));
    uint32_t b_kb  = (uint32_t)(((lane >> 3) & 1) * 16);

    load_chunk(sb, Ah, Al, Bh, Bl, arow0, brow0, Kdim, 0);

    for (int kc = 0; kc < nchunk; kc++) {
        asm volatile("cp.async.wait_group 0;" ::: "memory");
        __syncthreads();
#pragma unroll
        for (int ks = 0; ks < 4; ks++) {
            uint32_t aH[2][4], aL[2][4];
#pragma unroll
            for (int mi = 0; mi < 2; mi++) {
                uint32_t off = swz((uint32_t)((wm * 32 + mi * 16 + a_row) * 128 + ks * 32 + a_kb));
                ldsm4(aH[mi], sb + off);
                ldsm4(aL[mi], sb + OFF_AL + off);
            }
#pragma unroll
            for (int np = 0; np < 4; np++) {
                uint32_t off = swz((uint32_t)((wn * 64 + np * 16 + b_row) * 128 + ks * 32 + b_kb));
                uint32_t bh[4], bl[4];
                ldsm4(bh, sb + OFF_BH + off);
                ldsm4(bl, sb + OFF_BL + off);
#pragma unroll
                for (int mi = 0; mi < 2; mi++) {
                    mma16816(acc[mi][np*2],   aH[mi], bh);
                    mma16816(acc[mi][np*2],   aH[mi], bl);
                    mma16816(acc[mi][np*2],   aL[mi], bh);
                    mma16816(acc[mi][np*2+1], aH[mi], bh + 2);
                    mma16816(acc[mi][np*2+1], aH[mi], bl + 2);
                    mma16816(acc[mi][np*2+1], aL[mi], bh + 2);
                }
            }
        }
        __syncthreads();
        if (kc + 1 < nchunk)
            load_chunk(sb, Ah, Al, Bh, Bl, arow0, brow0, Kdim, kc + 1);
    }
}

// ===================== prep: split weights to bf16 planes =====================
__global__ void prep_kernel(const float* __restrict__ w2, const float* __restrict__ w3,
                            const float* __restrict__ w4)
{
    int i = blockIdx.x * 256 + threadIdx.x;
    int stride = gridDim.x * 256;
    for (int j = i; j < 256*128; j += stride) {
        uint32_t h, l; bsplit(w2[j], h, l);
        B2h[j] = __ushort_as_bfloat16((unsigned short)h);
        B2l[j] = __ushort_as_bfloat16((unsigned short)l);
    }
    for (int j = i; j < 512*512; j += stride) {
        int n = j >> 9, k = j & 511;
        uint32_t h, l; bsplit(w3[j], h, l);
        if (k < 256) {
            W3gh[n*256 + k] = __ushort_as_bfloat16((unsigned short)h);
            W3gl[n*256 + k] = __ushort_as_bfloat16((unsigned short)l);
        } else {
            W3fh[n*256 + k - 256] = __ushort_as_bfloat16((unsigned short)h);
            W3fl[n*256 + k - 256] = __ushort_as_bfloat16((unsigned short)l);
        }
    }
    for (int j = i; j < 384*512; j += stride) {
        uint32_t h, l; bsplit(w4[j], h, l);
        W4h[j] = __ushort_as_bfloat16((unsigned short)h);
        W4l[j] = __ushort_as_bfloat16((unsigned short)l);
    }
}

// ===================== FPS (points in smem) =====================
__global__ __launch_bounds__(1024) void fps_kernel(
    const float* __restrict__ pts, float* __restrict__ centers)
{
    extern __shared__ float sp[];   // [NP*3]
    int b = blockIdx.x;
    int t = threadIdx.x;
    const float* P = pts + (size_t)b * NP * 3;

    for (int idx = t; idx < NP * 3; idx += 1024) sp[idx] = P[idx];
    __syncthreads();

    float px[8], py[8], pz[8], md[8];
#pragma unroll
    for (int j = 0; j < 8; j++) {
        int n = j * 1024 + t;
        px[j] = sp[n*3+0]; py[j] = sp[n*3+1]; pz[j] = sp[n*3+2];
        md[j] = 1e10f;
    }

    __shared__ float s_val[32];
    __shared__ int   s_idx[32];
    __shared__ float s_c[3];
    __shared__ int   s_last;

    int last = 0;
    for (int s = 0; s < NG; s++) {
        if (t == 0) {
            float cx = sp[last*3+0], cy = sp[last*3+1], cz = sp[last*3+2];
            s_c[0] = cx; s_c[1] = cy; s_c[2] = cz;
            float* C = centers + ((size_t)b * NG + s) * 3;
            C[0] = cx; C[1] = cy; C[2] = cz;
        }
        __syncthreads();
        float cx = s_c[0], cy = s_c[1], cz = s_c[2];

        float bv = NEG_INF; int bi = 0x7fffffff;
#pragma unroll
        for (int j = 0; j < 8; j++) {
            float dx = px[j] - cx, dy = py[j] - cy, dz = pz[j] - cz;
            float d2 = fmaf(dz, dz, fmaf(dy, dy, __fmul_rn(dx, dx)));
            md[j] = fminf(md[j], d2);
            int n = j * 1024 + t;
            if (md[j] > bv || (md[j] == bv && n < bi)) { bv = md[j]; bi = n; }
        }
#pragma unroll
        for (int off = 16; off; off >>= 1) {
            float ov = __shfl_down_sync(0xffffffffu, bv, off);
            int   oi = __shfl_down_sync(0xffffffffu, bi, off);
            if (ov > bv || (ov == bv && oi < bi)) { bv = ov; bi = oi; }
        }
        if ((t & 31) == 0) { s_val[t >> 5] = bv; s_idx[t >> 5] = bi; }
        __syncthreads();
        if (t < 32) {
            bv = s_val[t]; bi = s_idx[t];
#pragma unroll
            for (int off = 16; off; off >>= 1) {
                float ov = __shfl_down_sync(0xffffffffu, bv, off);
                int   oi = __shfl_down_sync(0xffffffffu, bi, off);
                if (ov > bv || (ov == bv && oi < bi)) { bv = ov; bi = oi; }
            }
            if (t == 0) s_last = bi;
        }
        __syncthreads();
        last = s_last;
    }
}

// ===================== grouping + stage1 (3->128, bn1+relu, split) =====================
__global__ __launch_bounds__(256) void group_kernel(
    const float* __restrict__ pts, const float* __restrict__ centers,
    const float* __restrict__ w1,
    const float* __restrict__ bn1g, const float* __restrict__ bn1b,
    const float* __restrict__ bn1m, const float* __restrict__ bn1v)
{
    __shared__ float d2s[NP];
    __shared__ float rv[8];
    __shared__ int   ri[8];
    __shared__ int   sel[NK];
    __shared__ float PTS[NK*3];

    int m = blockIdx.x;
    int b = m >> 9;
    int t = threadIdx.x;
    const float* P = pts + (size_t)b * NP * 3;

    float cx = centers[m*3+0], cy = centers[m*3+1], cz = centers[m*3+2];
    float cn = fmaf(cz, cz, fmaf(cy, cy, __fmul_rn(cx, cx)));

#pragma unroll 4
    for (int j = 0; j < 32; j++) {
        int n = j * 256 + t;
        float x = P[n*3+0], y = P[n*3+1], z = P[n*3+2];
        float pn  = fmaf(z, z, fmaf(y, y, __fmul_rn(x, x)));
        float dot = fmaf(cz, z, fmaf(cy, y, __fmul_rn(cx, x)));
        d2s[n] = __fadd_rn(cn, pn) - 2.0f * dot;
    }
    __syncthreads();

    for (int p = 0; p < NK; p++) {
        float bv = POS_INF; int bi = 0x7fffffff;
#pragma unroll
        for (int j = 0; j < 32; j++) {
            int n = j * 256 + t;
            float v = d2s[n];
            if (v < bv || (v == bv && n < bi)) { bv = v; bi = n; }
        }
#pragma unroll
        for (int off = 16; off; off >>= 1) {
            float ov = __shfl_down_sync(0xffffffffu, bv, off);
            int   oi = __shfl_down_sync(0xffffffffu, bi, off);
            if (ov < bv || (ov == bv && oi < bi)) { bv = ov; bi = oi; }
        }
        if ((t & 31) == 0) { rv[t >> 5] = bv; ri[t >> 5] = bi; }
        __syncthreads();
        if (t == 0) {
            float fv = rv[0]; int fi = ri[0];
#pragma unroll
            for (int w = 1; w < 8; w++)
                if (rv[w] < fv || (rv[w] == fv && ri[w] < fi)) { fv = rv[w]; fi = ri[w]; }
            sel[p] = fi;
            d2s[fi] = POS_INF;
        }
        __syncthreads();
    }

    if (t < NK * 3) {
        int k = t / 3, c = t % 3;
        int n = sel[k];
        float cv = (c == 0) ? cx : (c == 1) ? cy : cz;
        PTS[t] = P[n*3+c] - cv;
    }
    __syncthreads();

    {
        int c  = t >> 1;
        int k0 = (t & 1) * 16;
        float wx = w1[c*3+0], wy = w1[c*3+1], wz = w1[c*3+2];
        float sc = bn1g[c] * rsqrtf(bn1v[c] + 1e-5f);
        float sh = fmaf(-bn1m[c], sc, bn1b[c]);
#pragma unroll
        for (int kk = 0; kk < 16; kk++) {
            int k = k0 + kk;
            float v = fmaf(PTS[k*3+2], wz, fmaf(PTS[k*3+1], wy, PTS[k*3+0] * wx));
            v = fmaxf(fmaf(v, sc, sh), 0.f);
            uint32_t h, l; bsplit(v, h, l);
            size_t o = ((size_t)m * NK + k) * 128 + c;
            F1h[o] = __ushort_as_bfloat16((unsigned short)h);
            F1l[o] = __ushort_as_bfloat16((unsigned short)l);
        }
    }
}

// ===================== GEMM kernels (register epilogues) =====================
// fragment: rows rb+mi*16+{0,8}, cols cb+ni*8+{0,1}; group gi == wm.

// gemm2: F2 = F1 @ W2^T + b2 ; GM = per-group max of F2
__global__ __launch_bounds__(256, 2) void gemm2_kernel(const float* __restrict__ b2)
{
    int mtile = blockIdx.x >> 1, nt = blockIdx.x & 1;
    float acc[2][8][4] = {};
    gemm_core(acc, F1h, F1l, B2h, B2l, mtile*128, nt*128, 128, 2);

    int t = threadIdx.x, lane = t & 31;
    int wm = (t >> 5) & 3, wn = t >> 7;
    int rb = wm*32 + (lane >> 2);
    int g  = mtile*4 + wm;
#pragma unroll
    for (int ni = 0; ni < 8; ni++) {
        int c = nt*128 + wn*64 + ni*8 + (lane & 3)*2;
        float bb0 = b2[c], bb1 = b2[c+1];
        float g0 = NEG_INF, g1 = NEG_INF;
#pragma unroll
        for (int mi = 0; mi < 2; mi++) {
            size_t row = (size_t)mtile*128 + rb + mi*16;
            float v0 = acc[mi][ni][0] + bb0, v1 = acc[mi][ni][1] + bb1;
            float v2 = acc[mi][ni][2] + bb0, v3 = acc[mi][ni][3] + bb1;
            uint32_t hw, lw;
            split2(v0, v1, hw, lw);
            *(uint32_t*)(F2h + row*256 + c) = hw;
            *(uint32_t*)(F2l + row*256 + c) = lw;
            split2(v2, v3, hw, lw);
            *(uint32_t*)(F2h + (row+8)*256 + c) = hw;
            *(uint32_t*)(F2l + (row+8)*256 + c) = lw;
            g0 = fmaxf(g0, fmaxf(v0, v2));
            g1 = fmaxf(g1, fmaxf(v1, v3));
        }
#pragma unroll
        for (int off = 4; off <= 16; off <<= 1) {
            g0 = fmaxf(g0, __shfl_xor_sync(0xffffffffu, g0, off));
            g1 = fmaxf(g1, __shfl_xor_sync(0xffffffffu, g1, off));
        }
        if (lane < 4) {
            uint32_t hw, lw; split2(g0, g1, hw, lw);
            *(uint32_t*)(GMh + (size_t)g*256 + c) = hw;
            *(uint32_t*)(GMl + (size_t)g*256 + c) = lw;
        }
    }
}

// gemm3g: G3 = GM @ W3g^T  (M = 8192 group rows)
__global__ __launch_bounds__(256, 2) void gemm3g_kernel()
{
    int mtile = blockIdx.x >> 2, nt = blockIdx.x & 3;
    float acc[2][8][4] = {};
    gemm_core(acc, GMh, GMl, W3gh, W3gl, mtile*128, nt*128, 256, 4);

    int t = threadIdx.x, lane = t & 31;
    int wm = (t >> 5) & 3, wn = t >> 7;
    int rb = wm*32 + (lane >> 2);
#pragma unroll
    for (int ni = 0; ni < 8; ni++) {
        int c = nt*128 + wn*64 + ni*8 + (lane & 3)*2;
#pragma unroll
        for (int mi = 0; mi < 2; mi++) {
            size_t row = (size_t)mtile*128 + rb + mi*16;
            *(float2*)(G3 + row*512 + c)     = make_float2(acc[mi][ni][0], acc[mi][ni][1]);
            *(float2*)(G3 + (row+8)*512 + c) = make_float2(acc[mi][ni][2], acc[mi][ni][3]);
        }
    }
}

// gemm3f: F3 = relu(bn2(F2 @ W3f^T + G3))
__global__ __launch_bounds__(256, 2) void gemm3f_kernel(
    const float* __restrict__ bn2g, const float* __restrict__ bn2b,
    const float* __restrict__ bn2m, const float* __restrict__ bn2v)
{
    int mtile = blockIdx.x >> 2, nt = blockIdx.x & 3;
    float acc[2][8][4] = {};
    gemm_core(acc, F2h, F2l, W3fh, W3fl, mtile*128, nt*128, 256, 4);

    // stage bn2 + G3 in (now free) smem buffer
    extern __shared__ char smem[];
    float* sSC = (float*)smem;        // [128]
    float* sSH = sSC + 128;           // [128]
    float* sG  = sSH + 128;           // [4][128]
    int t = threadIdx.x;
    if (t < 128) {
        int nl = nt*128 + t;
        float sc = bn2g[nl] * rsqrtf(bn2v[nl] + 1e-5f);
        sSC[t] = sc;
        sSH[t] = fmaf(-bn2m[nl], sc, bn2b[nl]);
    }
#pragma unroll
    for (int e = t; e < 512; e += 256)
        sG[e] = G3[(size_t)(mtile*4 + (e >> 7))*512 + nt*128 + (e & 127)];
    __syncthreads();

    int lane = t & 31;
    int wm = (t >> 5) & 3, wn = t >> 7;
    int rb = wm*32 + (lane >> 2);
#pragma unroll
    for (int ni = 0; ni < 8; ni++) {
        int lc = wn*64 + ni*8 + (lane & 3)*2;
        int c  = nt*128 + lc;
        float sc0 = sSC[lc], sc1 = sSC[lc+1];
        float sh0 = sSH[lc], sh1 = sSH[lc+1];
        float gv0 = sG[wm*128 + lc], gv1 = sG[wm*128 + lc + 1];
#pragma unroll
        for (int mi = 0; mi < 2; mi++) {
            size_t row = (size_t)mtile*128 + rb + mi*16;
            float v0 = fmaxf(fmaf(acc[mi][ni][0] + gv0, sc0, sh0), 0.f);
            float v1 = fmaxf(fmaf(acc[mi][ni][1] + gv1, sc1, sh1), 0.f);
            float v2 = fmaxf(fmaf(acc[mi][ni][2] + gv0, sc0, sh0), 0.f);
            float v3 = fmaxf(fmaf(acc[mi][ni][3] + gv1, sc1, sh1), 0.f);
            uint32_t hw, lw;
            split2(v0, v1, hw, lw);
            *(uint32_t*)(F3h + row*512 + c) = hw;
            *(uint32_t*)(F3l + row*512 + c) = lw;
            split2(v2, v3, hw, lw);
            *(uint32_t*)(F3h + (row+8)*512 + c) = hw;
            *(uint32_t*)(F3l + (row+8)*512 + c) = lw;
        }
    }
}

// gemm4: tokens = per-group max of (F3 @ W4^T + b4)
__global__ __launch_bounds__(256, 2) void gemm4_kernel(const float* __restrict__ b4,
                                                       float* __restrict__ tokens)
{
    int mtile = blockIdx.x / 3, nt = blockIdx.x % 3;
    float acc[2][8][4] = {};
    gemm_core(acc, F3h, F3l, W4h, W4l, mtile*128, nt*128, 512, 8);

    int t = threadIdx.x, lane = t & 31;
    int wm = (t >> 5) & 3, wn = t >> 7;
    int g = mtile*4 + wm;
#pragma unroll
    for (int ni = 0; ni < 8; ni++) {
        int c = nt*128 + wn*64 + ni*8 + (lane & 3)*2;
        float bb0 = b4[c], bb1 = b4[c+1];
        float g0 = NEG_INF, g1 = NEG_INF;
#pragma unroll
        for (int mi = 0; mi < 2; mi++) {
            g0 = fmaxf(g0, fmaxf(acc[mi][ni][0], acc[mi][ni][2]));
            g1 = fmaxf(g1, fmaxf(acc[mi][ni][1], acc[mi][ni][3]));
        }
        g0 += bb0; g1 += bb1;
#pragma unroll
        for (int off = 4; off <= 16; off <<= 1) {
            g0 = fmaxf(g0, __shfl_xor_sync(0xffffffffu, g0, off));
            g1 = fmaxf(g1, __shfl_xor_sync(0xffffffffu, g1, off));
        }
        if (lane < 4)
            *(float2*)(tokens + (size_t)g*TOK + c) = make_float2(g0, g1);
    }
}

// =====================================================================
extern "C" void kernel_launch(void* const* d_in, const int* in_sizes, int n_in,
                              void* d_out, int out_size)
{
    const float* points = (const float*)d_in[0];
    const float* w1     = (const float*)d_in[1];
    const float* bn1g   = (const float*)d_in[2];
    const float* bn1b   = (const float*)d_in[3];
    const float* bn1m   = (const float*)d_in[4];
    const float* bn1v   = (const float*)d_in[5];
    const float* w2     = (const float*)d_in[6];
    const float* b2     = (const float*)d_in[7];
    const float* w3     = (const float*)d_in[8];
    const float* bn2g   = (const float*)d_in[9];
    const float* bn2b   = (const float*)d_in[10];
    const float* bn2m   = (const float*)d_in[11];
    const float* bn2v   = (const float*)d_in[12];
    const float* w4     = (const float*)d_in[13];
    const float* b4     = (const float*)d_in[14];

    float* tokens  = (float*)d_out;                      // [B,G,384]
    float* centers = (float*)d_out + (size_t)NM * TOK;   // [B,G,3]

    static bool attr_done = false;
    if (!attr_done) {
        cudaFuncSetAttribute(fps_kernel,    cudaFuncAttributeMaxDynamicSharedMemorySize, NP*3*4);
        cudaFuncSetAttribute(gemm2_kernel,  cudaFuncAttributeMaxDynamicSharedMemorySize, GSMEM);
        cudaFuncSetAttribute(gemm3g_kernel, cudaFuncAttributeMaxDynamicSharedMemorySize, GSMEM);
        cudaFuncSetAttribute(gemm3f_kernel, cudaFuncAttributeMaxDynamicSharedMemorySize, GSMEM);
        cudaFuncSetAttribute(gemm4_kernel,  cudaFuncAttributeMaxDynamicSharedMemorySize, GSMEM);
        attr_done = true;
    }

    prep_kernel<<<256, 256>>>(w2, w3, w4);
    fps_kernel<<<NB, 1024, NP*3*4>>>(points, centers);
    group_kernel<<<NM, 256>>>(points, centers, w1, bn1g, bn1b, bn1m, bn1v);
    gemm2_kernel <<<4096, 256, GSMEM>>>(b2);
    gemm3g_kernel<<<256,  256, GSMEM>>>();
    gemm3f_kernel<<<8192, 256, GSMEM>>>(bn2g, bn2b, bn2m, bn2v);
    gemm4_kernel <<<6144, 256, GSMEM>>>(b4, tokens);
}

// round 7
// speedup vs baseline: 3.6943x; 1.0220x over previous
#include <cuda_runtime.h>
#include <cuda_bf16.h>
#include <cstdint>

#define NB 16
#define NP 8192
#define NG 512
#define NK 32
#define TOK 384
#define NM (NB*NG)          // 8192 groups
#define MTOT (NM*NK)        // 262144 rows

#define NEG_INF __int_as_float(0xff800000)
#define POS_INF __int_as_float(0x7f800000)

typedef __nv_bfloat16 bf16;
typedef unsigned long long ull;

// ===================== global scratch (bf16 split planes) =====================
__device__ __align__(16) bf16 F1h[(size_t)MTOT*128];
__device__ __align__(16) bf16 F1l[(size_t)MTOT*128];
__device__ __align__(16) bf16 F2h[(size_t)MTOT*256];
__device__ __align__(16) bf16 F2l[(size_t)MTOT*256];
__device__ __align__(16) bf16 F3h[(size_t)MTOT*512];
__device__ __align__(16) bf16 F3l[(size_t)MTOT*512];
__device__ __align__(16) bf16 GMh[(size_t)NM*256];
__device__ __align__(16) bf16 GMl[(size_t)NM*256];
__device__ __align__(16) float G3[(size_t)NM*512];
__device__ __align__(16) bf16 B2h[256*128],  B2l[256*128];
__device__ __align__(16) bf16 W3gh[512*256], W3gl[512*256];
__device__ __align__(16) bf16 W3fh[512*256], W3fl[512*256];
__device__ __align__(16) bf16 W4h[384*512],  W4l[384*512];

// ===================== helpers =====================
__device__ __forceinline__ uint32_t smem_u32(const void* p) {
    uint32_t a;
    asm("{ .reg .u64 t; cvta.to.shared.u64 t, %1; cvt.u32.u64 %0, t; }" : "=r"(a) : "l"(p));
    return a;
}
__device__ __forceinline__ uint32_t swz64(uint32_t o) { return o ^ ((o >> 3) & 0x30); }

__device__ __forceinline__ void cp16(uint32_t d, const void* s) {
    asm volatile("cp.async.cg.shared.global [%0], [%1], 16;" :: "r"(d), "l"(s));
}
__device__ __forceinline__ void ldsm4(uint32_t* r, uint32_t addr) {
    asm volatile("ldmatrix.sync.aligned.m8n8.x4.shared.b16 {%0,%1,%2,%3}, [%4];"
        : "=r"(r[0]), "=r"(r[1]), "=r"(r[2]), "=r"(r[3]) : "r"(addr));
}
__device__ __forceinline__ void mma16816(float* d, const uint32_t* a, const uint32_t* b) {
    asm volatile("mma.sync.aligned.m16n8k16.row.col.f32.bf16.bf16.f32 "
        "{%0,%1,%2,%3}, {%4,%5,%6,%7}, {%8,%9}, {%0,%1,%2,%3};"
        : "+f"(d[0]), "+f"(d[1]), "+f"(d[2]), "+f"(d[3])
        : "r"(a[0]), "r"(a[1]), "r"(a[2]), "r"(a[3]), "r"(b[0]), "r"(b[1]));
}
__device__ __forceinline__ void bsplit(float v, uint32_t& hb, uint32_t& lb) {
    bf16 h = __float2bfloat16_rn(v);
    float hf = __bfloat162float(h);
    bf16 l = __float2bfloat16_rn(v - hf);
    hb = (uint32_t)__bfloat16_as_ushort(h);
    lb = (uint32_t)__bfloat16_as_ushort(l);
}
__device__ __forceinline__ void split2(float v0, float v1, uint32_t& hw, uint32_t& lw) {
    uint32_t h0, l0, h1, l1;
    bsplit(v0, h0, l0); bsplit(v1, h1, l1);
    hw = h0 | (h1 << 16); lw = l0 | (l1 << 16);
}

// ===================== HMMA GEMM core =====================
// CTA tile M128 x N128, K chunk 32, 2-stage cp.async pipeline.
// Stage (32KB): Ah @0, Al @8K, Bh @16K, Bl @24K. Stage1 @+32K. Total 64KB.
#define STG 32768
#define GSMEM 65536

__device__ __forceinline__ void load_chunk32(uint32_t base,
    const bf16* __restrict__ Ah, const bf16* __restrict__ Al,
    const bf16* __restrict__ Bh, const bf16* __restrict__ Bl,
    int arow0, int brow0, int Kdim, int kc)
{
    int t = threadIdx.x;
#pragma unroll
    for (int it = 0; it < 8; it++) {
        int idx = t + it * 256;          // 0..2047
        int arr = idx >> 9;              // 0=Ah 1=Al 2=Bh 3=Bl
        int r   = (idx >> 2) & 127;
        int c   = idx & 3;
        uint32_t so = swz64((uint32_t)(r * 64 + c * 16));
        const bf16* src = (arr == 0) ? Ah : (arr == 1) ? Al : (arr == 2) ? Bh : Bl;
        int row0 = (arr < 2) ? arow0 : brow0;
        cp16(base + arr * 8192 + so, src + (size_t)(row0 + r) * Kdim + kc * 32 + c * 8);
    }
    asm volatile("cp.async.commit_group;" ::: "memory");
}

__device__ __forceinline__ void gemm_core(float acc[2][8][4],
    const bf16* __restrict__ Ah, const bf16* __restrict__ Al,
    const bf16* __restrict__ Bh, const bf16* __restrict__ Bl,
    int arow0, int brow0, int Kdim, int nchunk)   // nchunk in K32 units
{
    extern __shared__ char smem[];
    uint32_t sb = smem_u32(smem);
    int t = threadIdx.x, lane = t & 31;
    int wm = (t >> 5) & 3, wn = t >> 7;

    uint32_t a_row = (uint32_t)(lane & 15);
    uint32_t a_kb  = (uint32_t)((lane >> 4) * 16);
    uint32_t b_row = (uint32_t)((lane & 7) + ((lane & 16) ? 8 : 0));
    uint32_t b_kb  = (uint32_t)(((lane >> 3) & 1) * 16);

    load_chunk32(sb,       Ah, Al, Bh, Bl, arow0, brow0, Kdim, 0);
    load_chunk32(sb + STG, Ah, Al, Bh, Bl, arow0, brow0, Kdim, 1);

    for (int kc = 0; kc < nchunk; kc++) {
        if (kc + 1 < nchunk) { asm volatile("cp.async.wait_group 1;" ::: "memory"); }
        else                 { asm volatile("cp.async.wait_group 0;" ::: "memory"); }
        __syncthreads();
        uint32_t base = sb + (kc & 1) * STG;
#pragma unroll
        for (int ks = 0; ks < 2; ks++) {
            uint32_t aH[2][4], aL[2][4];
#pragma unroll
            for (int mi = 0; mi < 2; mi++) {
                uint32_t off = swz64((uint32_t)((wm * 32 + mi * 16 + a_row) * 64 + ks * 32 + a_kb));
                ldsm4(aH[mi], base + off);
                ldsm4(aL[mi], base + 8192 + off);
            }
#pragma unroll
            for (int np = 0; np < 4; np++) {
                uint32_t off = swz64((uint32_t)((wn * 64 + np * 16 + b_row) * 64 + ks * 32 + b_kb));
                uint32_t bh[4], bl[4];
                ldsm4(bh, base + 16384 + off);
                ldsm4(bl, base + 24576 + off);
#pragma unroll
                for (int mi = 0; mi < 2; mi++) {
                    mma16816(acc[mi][np*2],   aH[mi], bh);
                    mma16816(acc[mi][np*2],   aH[mi], bl);
                    mma16816(acc[mi][np*2],   aL[mi], bh);
                    mma16816(acc[mi][np*2+1], aH[mi], bh + 2);
                    mma16816(acc[mi][np*2+1], aH[mi], bl + 2);
                    mma16816(acc[mi][np*2+1], aL[mi], bh + 2);
                }
            }
        }
        __syncthreads();
        if (kc + 2 < nchunk)
            load_chunk32(base, Ah, Al, Bh, Bl, arow0, brow0, Kdim, kc + 2);
    }
}

// ===================== prep: split weights to bf16 planes =====================
__global__ void prep_kernel(const float* __restrict__ w2, const float* __restrict__ w3,
                            const float* __restrict__ w4)
{
    int i = blockIdx.x * 256 + threadIdx.x;
    int stride = gridDim.x * 256;
    for (int j = i; j < 256*128; j += stride) {
        uint32_t h, l; bsplit(w2[j], h, l);
        B2h[j] = __ushort_as_bfloat16((unsigned short)h);
        B2l[j] = __ushort_as_bfloat16((unsigned short)l);
    }
    for (int j = i; j < 512*512; j += stride) {
        int n = j >> 9, k = j & 511;
        uint32_t h, l; bsplit(w3[j], h, l);
        if (k < 256) {
            W3gh[n*256 + k] = __ushort_as_bfloat16((unsigned short)h);
            W3gl[n*256 + k] = __ushort_as_bfloat16((unsigned short)l);
        } else {
            W3fh[n*256 + k - 256] = __ushort_as_bfloat16((unsigned short)h);
            W3fl[n*256 + k - 256] = __ushort_as_bfloat16((unsigned short)l);
        }
    }
    for (int j = i; j < 384*512; j += stride) {
        uint32_t h, l; bsplit(w4[j], h, l);
        W4h[j] = __ushort_as_bfloat16((unsigned short)h);
        W4l[j] = __ushort_as_bfloat16((unsigned short)l);
    }
}

// ===================== FPS (points in smem, packed u64 argmax) =====================
__global__ __launch_bounds__(1024) void fps_kernel(
    const float* __restrict__ pts, float* __restrict__ centers)
{
    extern __shared__ float sp[];   // [NP*3]
    int b = blockIdx.x;
    int t = threadIdx.x;
    const float* P = pts + (size_t)b * NP * 3;

    for (int idx = t; idx < NP * 3; idx += 1024) sp[idx] = P[idx];
    __syncthreads();

    float px[8], py[8], pz[8], md[8];
#pragma unroll
    for (int j = 0; j < 8; j++) {
        int n = j * 1024 + t;
        px[j] = sp[n*3+0]; py[j] = sp[n*3+1]; pz[j] = sp[n*3+2];
        md[j] = 1e10f;
    }

    __shared__ ull s_pk[32];
    __shared__ int s_last;

    int last = 0;
    for (int s = 0; s < NG; s++) {
        float cx = sp[last*3+0], cy = sp[last*3+1], cz = sp[last*3+2];
        if (t == 0) {
            float* C = centers + ((size_t)b * NG + s) * 3;
            C[0] = cx; C[1] = cy; C[2] = cz;
        }

        ull best = 0;
#pragma unroll
        for (int j = 0; j < 8; j++) {
            float dx = px[j] - cx, dy = py[j] - cy, dz = pz[j] - cz;
            float d2 = fmaf(dz, dz, fmaf(dy, dy, __fmul_rn(dx, dx)));
            md[j] = fminf(md[j], d2);
            int n = j * 1024 + t;
            ull p = ((ull)__float_as_uint(md[j]) << 32) | (uint32_t)(~n);
            best = (p > best) ? p : best;
        }
#pragma unroll
        for (int off = 16; off; off >>= 1) {
            ull o = __shfl_down_sync(0xffffffffu, best, off);
            best = (o > best) ? o : best;
        }
        if ((t & 31) == 0) s_pk[t >> 5] = best;
        __syncthreads();
        if (t < 32) {
            best = s_pk[t];
#pragma unroll
            for (int off = 16; off; off >>= 1) {
                ull o = __shfl_down_sync(0xffffffffu, best, off);
                best = (o > best) ? o : best;
            }
            if (t == 0) s_last = (int)(uint32_t)(~(uint32_t)best);
        }
        __syncthreads();
        last = s_last;
    }
}

// ===================== grouping + stage1 (3->128, bn1+relu, split) =====================
__global__ __launch_bounds__(256) void group_kernel(
    const float* __restrict__ pts, const float* __restrict__ centers,
    const float* __restrict__ w1,
    const float* __restrict__ bn1g, const float* __restrict__ bn1b,
    const float* __restrict__ bn1m, const float* __restrict__ bn1v)
{
    __shared__ float d2s[NP];
    __shared__ float rv[8];
    __shared__ int   ri[8];
    __shared__ int   sel[NK];
    __shared__ float PTS[NK*3];

    int m = blockIdx.x;
    int b = m >> 9;
    int t = threadIdx.x;
    const float* P = pts + (size_t)b * NP * 3;

    float cx = centers[m*3+0], cy = centers[m*3+1], cz = centers[m*3+2];
    float cn = fmaf(cz, cz, fmaf(cy, cy, __fmul_rn(cx, cx)));

#pragma unroll 4
    for (int j = 0; j < 32; j++) {
        int n = j * 256 + t;
        float x = P[n*3+0], y = P[n*3+1], z = P[n*3+2];
        float pn  = fmaf(z, z, fmaf(y, y, __fmul_rn(x, x)));
        float dot = fmaf(cz, z, fmaf(cy, y, __fmul_rn(cx, x)));
        d2s[n] = __fadd_rn(cn, pn) - 2.0f * dot;
    }
    __syncthreads();

    for (int p = 0; p < NK; p++) {
        float bv = POS_INF; int bi = 0x7fffffff;
#pragma unroll
        for (int j = 0; j < 32; j++) {
            int n = j * 256 + t;
            float v = d2s[n];
            if (v < bv || (v == bv && n < bi)) { bv = v; bi = n; }
        }
#pragma unroll
        for (int off = 16; off; off >>= 1) {
            float ov = __shfl_down_sync(0xffffffffu, bv, off);
            int   oi = __shfl_down_sync(0xffffffffu, bi, off);
            if (ov < bv || (ov == bv && oi < bi)) { bv = ov; bi = oi; }
        }
        if ((t & 31) == 0) { rv[t >> 5] = bv; ri[t >> 5] = bi; }
        __syncthreads();
        if (t == 0) {
            float fv = rv[0]; int fi = ri[0];
#pragma unroll
            for (int w = 1; w < 8; w++)
                if (rv[w] < fv || (rv[w] == fv && ri[w] < fi)) { fv = rv[w]; fi = ri[w]; }
            sel[p] = fi;
            d2s[fi] = POS_INF;
        }
        __syncthreads();
    }

    if (t < NK * 3) {
        int k = t / 3, c = t % 3;
        int n = sel[k];
        float cv = (c == 0) ? cx : (c == 1) ? cy : cz;
        PTS[t] = P[n*3+c] - cv;
    }
    __syncthreads();

    {
        int c  = t >> 1;
        int k0 = (t & 1) * 16;
        float wx = w1[c*3+0], wy = w1[c*3+1], wz = w1[c*3+2];
        float sc = bn1g[c] * rsqrtf(bn1v[c] + 1e-5f);
        float sh = fmaf(-bn1m[c], sc, bn1b[c]);
#pragma unroll
        for (int kk = 0; kk < 16; kk++) {
            int k = k0 + kk;
            float v = fmaf(PTS[k*3+2], wz, fmaf(PTS[k*3+1], wy, PTS[k*3+0] * wx));
            v = fmaxf(fmaf(v, sc, sh), 0.f);
            uint32_t h, l; bsplit(v, h, l);
            size_t o = ((size_t)m * NK + k) * 128 + c;
            F1h[o] = __ushort_as_bfloat16((unsigned short)h);
            F1l[o] = __ushort_as_bfloat16((unsigned short)l);
        }
    }
}

// ===================== GEMM kernels (register epilogues) =====================

// gemm2: F2 = F1 @ W2^T + b2 ; GM = per-group max of F2
__global__ __launch_bounds__(256, 2) void gemm2_kernel(const float* __restrict__ b2)
{
    int mtile = blockIdx.x >> 1, nt = blockIdx.x & 1;
    float acc[2][8][4] = {};
    gemm_core(acc, F1h, F1l, B2h, B2l, mtile*128, nt*128, 128, 4);

    int t = threadIdx.x, lane = t & 31;
    int wm = (t >> 5) & 3, wn = t >> 7;
    int rb = wm*32 + (lane >> 2);
    int g  = mtile*4 + wm;
#pragma unroll
    for (int ni = 0; ni < 8; ni++) {
        int c = nt*128 + wn*64 + ni*8 + (lane & 3)*2;
        float bb0 = b2[c], bb1 = b2[c+1];
        float g0 = NEG_INF, g1 = NEG_INF;
#pragma unroll
        for (int mi = 0; mi < 2; mi++) {
            size_t row = (size_t)mtile*128 + rb + mi*16;
            float v0 = acc[mi][ni][0] + bb0, v1 = acc[mi][ni][1] + bb1;
            float v2 = acc[mi][ni][2] + bb0, v3 = acc[mi][ni][3] + bb1;
            uint32_t hw, lw;
            split2(v0, v1, hw, lw);
            *(uint32_t*)(F2h + row*256 + c) = hw;
            *(uint32_t*)(F2l + row*256 + c) = lw;
            split2(v2, v3, hw, lw);
            *(uint32_t*)(F2h + (row+8)*256 + c) = hw;
            *(uint32_t*)(F2l + (row+8)*256 + c) = lw;
            g0 = fmaxf(g0, fmaxf(v0, v2));
            g1 = fmaxf(g1, fmaxf(v1, v3));
        }
#pragma unroll
        for (int off = 4; off <= 16; off <<= 1) {
            g0 = fmaxf(g0, __shfl_xor_sync(0xffffffffu, g0, off));
            g1 = fmaxf(g1, __shfl_xor_sync(0xffffffffu, g1, off));
        }
        if (lane < 4) {
            uint32_t hw, lw; split2(g0, g1, hw, lw);
            *(uint32_t*)(GMh + (size_t)g*256 + c) = hw;
            *(uint32_t*)(GMl + (size_t)g*256 + c) = lw;
        }
    }
}

// gemm3g: G3 = GM @ W3g^T  (M = 8192 group rows)
__global__ __launch_bounds__(256, 2) void gemm3g_kernel()
{
    int mtile = blockIdx.x >> 2, nt = blockIdx.x & 3;
    float acc[2][8][4] = {};
    gemm_core(acc, GMh, GMl, W3gh, W3gl, mtile*128, nt*128, 256, 8);

    int t = threadIdx.x, lane = t & 31;
    int wm = (t >> 5) & 3, wn = t >> 7;
    int rb = wm*32 + (lane >> 2);
#pragma unroll
    for (int ni = 0; ni < 8; ni++) {
        int c = nt*128 + wn*64 + ni*8 + (lane & 3)*2;
#pragma unroll
        for (int mi = 0; mi < 2; mi++) {
            size_t row = (size_t)mtile*128 + rb + mi*16;
            *(float2*)(G3 + row*512 + c)     = make_float2(acc[mi][ni][0], acc[mi][ni][1]);
            *(float2*)(G3 + (row+8)*512 + c) = make_float2(acc[mi][ni][2], acc[mi][ni][3]);
        }
    }
}

// gemm3f: F3 = relu(bn2(F2 @ W3f^T + G3))
__global__ __launch_bounds__(256, 2) void gemm3f_kernel(
    const float* __restrict__ bn2g, const float* __restrict__ bn2b,
    const float* __restrict__ bn2m, const float* __restrict__ bn2v)
{
    int mtile = blockIdx.x >> 2, nt = blockIdx.x & 3;
    float acc[2][8][4] = {};
    gemm_core(acc, F2h, F2l, W3fh, W3fl, mtile*128, nt*128, 256, 8);

    // stage bn2 + G3 in (now idle) smem buffer
    extern __shared__ char smem[];
    float* sSC = (float*)smem;        // [128]
    float* sSH = sSC + 128;           // [128]
    float* sG  = sSH + 128;           // [4][128]
    int t = threadIdx.x;
    if (t < 128) {
        int nl = nt*128 + t;
        float sc = bn2g[nl] * rsqrtf(bn2v[nl] + 1e-5f);
        sSC[t] = sc;
        sSH[t] = fmaf(-bn2m[nl], sc, bn2b[nl]);
    }
#pragma unroll
    for (int e = t; e < 512; e += 256)
        sG[e] = G3[(size_t)(mtile*4 + (e >> 7))*512 + nt*128 + (e & 127)];
    __syncthreads();

    int lane = t & 31;
    int wm = (t >> 5) & 3, wn = t >> 7;
    int rb = wm*32 + (lane >> 2);
#pragma unroll
    for (int ni = 0; ni < 8; ni++) {
        int lc = wn*64 + ni*8 + (lane & 3)*2;
        int c  = nt*128 + lc;
        float sc0 = sSC[lc], sc1 = sSC[lc+1];
        float sh0 = sSH[lc], sh1 = sSH[lc+1];
        float gv0 = sG[wm*128 + lc], gv1 = sG[wm*128 + lc + 1];
#pragma unroll
        for (int mi = 0; mi < 2; mi++) {
            size_t row = (size_t)mtile*128 + rb + mi*16;
            float v0 = fmaxf(fmaf(acc[mi][ni][0] + gv0, sc0, sh0), 0.f);
            float v1 = fmaxf(fmaf(acc[mi][ni][1] + gv1, sc1, sh1), 0.f);
            float v2 = fmaxf(fmaf(acc[mi][ni][2] + gv0, sc0, sh0), 0.f);
            float v3 = fmaxf(fmaf(acc[mi][ni][3] + gv1, sc1, sh1), 0.f);
            uint32_t hw, lw;
            split2(v0, v1, hw, lw);
            *(uint32_t*)(F3h + row*512 + c) = hw;
            *(uint32_t*)(F3l + row*512 + c) = lw;
            split2(v2, v3, hw, lw);
            *(uint32_t*)(F3h + (row+8)*512 + c) = hw;
            *(uint32_t*)(F3l + (row+8)*512 + c) = lw;
        }
    }
}

// gemm4: tokens = per-group max of (F3 @ W4^T + b4)
__global__ __launch_bounds__(256, 2) void gemm4_kernel(const float* __restrict__ b4,
                                                       float* __restrict__ tokens)
{
    int mtile = blockIdx.x / 3, nt = blockIdx.x % 3;
    float acc[2][8][4] = {};
    gemm_core(acc, F3h, F3l, W4h, W4l, mtile*128, nt*128, 512, 16);

    int t = threadIdx.x, lane = t & 31;
    int wm = (t >> 5) & 3, wn = t >> 7;
    int g = mtile*4 + wm;
#pragma unroll
    for (int ni = 0; ni < 8; ni++) {
        int c = nt*128 + wn*64 + ni*8 + (lane & 3)*2;
        float bb0 = b4[c], bb1 = b4[c+1];
        float g0 = NEG_INF, g1 = NEG_INF;
#pragma unroll
        for (int mi = 0; mi < 2; mi++) {
            g0 = fmaxf(g0, fmaxf(acc[mi][ni][0], acc[mi][ni][2]));
            g1 = fmaxf(g1, fmaxf(acc[mi][ni][1], acc[mi][ni][3]));
        }
        g0 += bb0; g1 += bb1;
#pragma unroll
        for (int off = 4; off <= 16; off <<= 1) {
            g0 = fmaxf(g0, __shfl_xor_sync(0xffffffffu, g0, off));
            g1 = fmaxf(g1, __shfl_xor_sync(0xffffffffu, g1, off));
        }
        if (lane < 4)
            *(float2*)(tokens + (size_t)g*TOK + c) = make_float2(g0, g1);
    }
}

// =====================================================================
extern "C" void kernel_launch(void* const* d_in, const int* in_sizes, int n_in,
                              void* d_out, int out_size)
{
    const float* points = (const float*)d_in[0];
    const float* w1     = (const float*)d_in[1];
    const float* bn1g   = (const float*)d_in[2];
    const float* bn1b   = (const float*)d_in[3];
    const float* bn1m   = (const float*)d_in[4];
    const float* bn1v   = (const float*)d_in[5];
    const float* w2     = (const float*)d_in[6];
    const float* b2     = (const float*)d_in[7];
    const float* w3     = (const float*)d_in[8];
    const float* bn2g   = (const float*)d_in[9];
    const float* bn2b   = (const float*)d_in[10];
    const float* bn2m   = (const float*)d_in[11];
    const float* bn2v   = (const float*)d_in[12];
    const float* w4     = (const float*)d_in[13];
    const float* b4     = (const float*)d_in[14];

    float* tokens  = (float*)d_out;                      // [B,G,384]
    float* centers = (float*)d_out + (size_t)NM * TOK;   // [B,G,3]

    static bool attr_done = false;
    if (!attr_done) {
        cudaFuncSetAttribute(fps_kernel,    cudaFuncAttributeMaxDynamicSharedMemorySize, NP*3*4);
        cudaFuncSetAttribute(gemm2_kernel,  cudaFuncAttributeMaxDynamicSharedMemorySize, GSMEM);
        cudaFuncSetAttribute(gemm3g_kernel, cudaFuncAttributeMaxDynamicSharedMemorySize, GSMEM);
        cudaFuncSetAttribute(gemm3f_kernel, cudaFuncAttributeMaxDynamicSharedMemorySize, GSMEM);
        cudaFuncSetAttribute(gemm4_kernel,  cudaFuncAttributeMaxDynamicSharedMemorySize, GSMEM);
        attr_done = true;
    }

    prep_kernel<<<256, 256>>>(w2, w3, w4);
    fps_kernel<<<NB, 1024, NP*3*4>>>(points, centers);
    group_kernel<<<NM, 256>>>(points, centers, w1, bn1g, bn1b, bn1m, bn1v);
    gemm2_kernel <<<4096, 256, GSMEM>>>(b2);
    gemm3g_kernel<<<256,  256, GSMEM>>>();
    gemm3f_kernel<<<8192, 256, GSMEM>>>(bn2g, bn2b, bn2m, bn2v);
    gemm4_kernel <<<6144, 256, GSMEM>>>(b4, tokens);
}